// round 8
// baseline (speedup 1.0000x reference)
#include <cuda_runtime.h>
#include <cuda_fp16.h>

// Problem constants
#define GRID_HW 512
#define HWO     (GRID_HW * GRID_HW)          // 262144 = 2^18
#define NPIX    (4 * HWO)                    // 1048576 = 2^20
#define FEAT    16

// Level sizes (square textures)
#define W1 1024
#define W2 512
#define W3 256
#define W4 128
#define N1 (W1 * W1)
#define N2 (W2 * W2)
#define N3 (W3 * W3)
#define N4 (W4 * W4)

// Feature-interleaved fp16 packed textures: one texel = 16 halfs = 32B record
// stored as 2 x uint4 (features 0-7, 8-15). 42.5 MB total -> L2 resident.
__device__ __align__(16) static uint4 g_p1[N1 * 2];   // 32 MB
__device__ __align__(16) static uint4 g_p2[N2 * 2];   //  8 MB
__device__ __align__(16) static uint4 g_p3[N3 * 2];   //  2 MB
__device__ __align__(16) static uint4 g_p4[N4 * 2];   //  0.5 MB

// ---------------------------------------------------------------------------
// Fused repack: all 4 levels in one kernel. src (F, H, W) fp32 channel-major
// -> dst AoS fp16 records. FOUR consecutive texels per thread: one float4
// load per feature (16 LDG.128), 8 contiguous uint4 stores (128B). DRAM-bound
// at ~128 MB total traffic.
// ---------------------------------------------------------------------------
__global__ void __launch_bounds__(256) repack_fused_kernel(
    const float* __restrict__ t1, const float* __restrict__ t2,
    const float* __restrict__ t3, const float* __restrict__ t4) {
    int idx = blockIdx.x * blockDim.x + threadIdx.x;   // texel-quad index

    const float* src;
    uint4* dst;
    int quad, HW;
    const int Q1 = N1 / 4, Q2 = Q1 + N2 / 4, Q3 = Q2 + N3 / 4, Q4 = Q3 + N4 / 4;
    if (idx < Q1)      { src = t1; dst = g_p1; quad = idx;      HW = N1; }
    else if (idx < Q2) { src = t2; dst = g_p2; quad = idx - Q1; HW = N2; }
    else if (idx < Q3) { src = t3; dst = g_p3; quad = idx - Q2; HW = N3; }
    else if (idx < Q4) { src = t4; dst = g_p4; quad = idx - Q3; HW = N4; }
    else return;

    int lin = quad * 4;

    float4 a[FEAT];
#pragma unroll
    for (int f = 0; f < FEAT; f++)
        a[f] = __ldcs((const float4*)(src + (size_t)f * HW + lin));

#pragma unroll
    for (int r = 0; r < 4; r++) {
        const float* ap;
        half2 h[8];
#pragma unroll
        for (int f = 0; f < 8; f++) {
            float va, vb;
            ap = &a[2 * f].x;     vb = ap[r];   // feature 2f   (note: named vb/va order fixed below)
            va = ap[r];
            ap = &a[2 * f + 1].x; vb = ap[r];   // feature 2f+1
            h[f] = __floats2half2_rn(va, vb);
        }
        uint4 o;
        o.x = *reinterpret_cast<unsigned*>(&h[0]); o.y = *reinterpret_cast<unsigned*>(&h[1]);
        o.z = *reinterpret_cast<unsigned*>(&h[2]); o.w = *reinterpret_cast<unsigned*>(&h[3]);
        dst[(size_t)(lin + r) * 2 + 0] = o;
        o.x = *reinterpret_cast<unsigned*>(&h[4]); o.y = *reinterpret_cast<unsigned*>(&h[5]);
        o.z = *reinterpret_cast<unsigned*>(&h[6]); o.w = *reinterpret_cast<unsigned*>(&h[7]);
        dst[(size_t)(lin + r) * 2 + 1] = o;
    }
}

// ---------------------------------------------------------------------------
// Gather: one thread per (pixel, feature-half, x-side). t = p*4 + side*2 + h.
// Phase A: coords/weights/addresses for all 4 levels (derived-coordinate
// chain ix' = 0.5*ix - 0.25), all 8 LDG.128 issued back-to-back (MLP=8).
// Phase B: per level fold rows y0/y1 in half2, convert, fp32-accumulate
// scaled by this lane's x-side weight.
// Epilogue: shfl.xor(2) folds x-sides; BOTH side lanes store 4 features each.
// ---------------------------------------------------------------------------
__global__ void __launch_bounds__(256) gather_kernel(const float* __restrict__ grid,
                                                     float* __restrict__ out) {
    int t = blockIdx.x * blockDim.x + threadIdx.x;
    int p    = t >> 2;           // pixel 0..2^20-1
    int h    = t & 1;            // feature half
    int side = (t >> 1) & 1;     // x corner side

    float2 g = __ldcs((const float2*)grid + p);   // streaming: don't pollute L2

    const uint4* __restrict__ texs[4] = { g_p1, g_p2, g_p3, g_p4 };
    const int Ws[4] = { W1, W2, W3, W4 };

    // Unclamped level-1 coords; per-level derived by ix' = 0.5*ix - 0.25.
    float ix = ((g.x + 1.0f) * (float)W1 - 1.0f) * 0.5f;
    float iy = ((g.y + 1.0f) * (float)W1 - 1.0f) * 0.5f;

    uint4 u0[4], u1[4];
    half2 w0h[4], w1h[4];
    float wxs[4];

#pragma unroll
    for (int L = 0; L < 4; L++) {
        const int   W  = Ws[L];
        const float Wf = (float)W;
        float cx = fminf(fmaxf(ix, 0.0f), Wf - 1.0f);
        float cy = fminf(fmaxf(iy, 0.0f), Wf - 1.0f);
        float x0f = floorf(cx);
        float y0f = floorf(cy);
        float wx = cx - x0f;
        float wy = cy - y0f;
        int x0 = (int)x0f;
        int y0 = (int)y0f;
        int xs = side ? min(x0 + 1, W - 1) : x0;
        int y1 = min(y0 + 1, W - 1);

        wxs[L] = side ? wx : (1.0f - wx);
        w0h[L] = __float2half2_rn(1.0f - wy);
        w1h[L] = __float2half2_rn(wy);

        const uint4* base = texs[L];
        u0[L] = __ldg(base + ((y0 * W + xs) * 2 + h));
        u1[L] = __ldg(base + ((y1 * W + xs) * 2 + h));

        ix = ix * 0.5f - 0.25f;
        iy = iy * 0.5f - 0.25f;
    }

    float acc[8];
#pragma unroll
    for (int j = 0; j < 8; j++) acc[j] = 0.0f;

#pragma unroll
    for (int L = 0; L < 4; L++) {
        const half2* v0 = reinterpret_cast<const half2*>(&u0[L]);
        const half2* v1 = reinterpret_cast<const half2*>(&u1[L]);
        float ws = wxs[L];
#pragma unroll
        for (int k = 0; k < 4; k++) {
            half2 tk = __hfma2(v1[k], w1h[L], __hmul2(v0[k], w0h[L]));
            float2 tf = __half22float2(tk);
            acc[2 * k]     = fmaf(tf.x, ws, acc[2 * k]);
            acc[2 * k + 1] = fmaf(tf.y, ws, acc[2 * k + 1]);
        }
    }

    // Fold x-sides: lane (p, side, h) <-> (p, side^1, h). Both lanes get sum.
#pragma unroll
    for (int j = 0; j < 8; j++)
        acc[j] += __shfl_xor_sync(0xffffffffu, acc[j], 2);

    // All 32 lanes store: lane (h, side) owns features 8h + 4*side .. +4.
    int b  = p >> 18;            // batch
    int hw = p & (HWO - 1);
    int f0 = h * 8 + side * 4;
    size_t base = ((size_t)(b * FEAT + f0) << 18) | (unsigned)hw;
#pragma unroll
    for (int j = 0; j < 4; j++)
        __stcs(out + base + (size_t)j * HWO, acc[side * 4 + j]);  // streaming
}

extern "C" void kernel_launch(void* const* d_in, const int* in_sizes, int n_in,
                              void* d_out, int out_size) {
    const float* x    = (const float*)d_in[0];   // (4, 512, 512, 2)
    const float* tex1 = (const float*)d_in[1];   // (16, 1024, 1024)
    const float* tex2 = (const float*)d_in[2];   // (16, 512, 512)
    const float* tex3 = (const float*)d_in[3];   // (16, 256, 256)
    const float* tex4 = (const float*)d_in[4];   // (16, 128, 128)
    float* out = (float*)d_out;                  // (4, 16, 512, 512)

    // Fused repack: all levels -> fp16 AoS records. Four texels per thread.
    const int total_quads = (N1 + N2 + N3 + N4) / 4;   // 344,064
    repack_fused_kernel<<<(total_quads + 255) / 256, 256>>>(tex1, tex2, tex3, tex4);

    // Gather + blend + sum levels. One thread per (pixel, half, side).
    gather_kernel<<<(4 * NPIX) / 256, 256>>>(x, out);
}